// round 14
// baseline (speedup 1.0000x reference)
#include <cuda_runtime.h>
#include <stdint.h>

#define D 128        // feature dim: one warp = one row (32 lanes x float4)
#define NPASS 2      // output partitions (each 64 MB, held in L2 by evict_last)
#define W 4          // items per warp-iteration (R9 best: 40 regs, occ ~61%)

// Zero the out partition with evict_last stores: zeros allocate in L2 at top
// priority and never round-trip to DRAM before the atomics arrive.
__global__ void zero_evict_last_kernel(float4* __restrict__ out, long long n4) {
    unsigned long long pol;
    asm("createpolicy.fractional.L2::evict_last.b64 %0, 1.0;" : "=l"(pol));
    long long i = (long long)blockIdx.x * blockDim.x + threadIdx.x;
    long long stride = (long long)gridDim.x * blockDim.x;
    for (; i < n4; i += stride) {
        asm volatile("st.global.L2::cache_hint.v4.f32 [%0], {%1, %1, %1, %1}, %2;"
                     :: "l"(out + i), "f"(0.0f), "l"(pol) : "memory");
    }
}

__global__ void gather_scatter_pass_kernel(const float* __restrict__ x,
                                           const void* __restrict__ from_idx,
                                           const void* __restrict__ to_idx,
                                           float* __restrict__ out,
                                           int nnz,
                                           int num_from,
                                           int t_lo,
                                           int t_hi) {
    // Per-block index-dtype detection (int32 vs int64). Index values fit in
    // 32 bits, so for int64 data every odd 32-bit word is 0.
    __shared__ int s_is64;
    if (threadIdx.x == 0) {
        const unsigned int* w = (const unsigned int*)from_idx;
        s_is64 = (w[1] == 0u && w[3] == 0u && w[5] == 0u && w[7] == 0u) ? 1 : 0;
    }
    __syncthreads();
    const int is64 = s_is64;

    // evict_last policy for the atomic RMW: the out partition outranks the
    // streaming gather lines in L2 replacement, so gathers keep evict-normal
    // (capturing within-pass row reuse) without thrashing the partition.
    unsigned long long pol;
    asm("createpolicy.fractional.L2::evict_last.b64 %0, 1.0;" : "=l"(pol));

    const int gtid = blockIdx.x * blockDim.x + threadIdx.x;
    const int lane = threadIdx.x & 31;
    const int i = gtid;  // each LANE owns one nonzero (coalesced index loads)

    int f = 0, t = -1;
    if (i < nnz) {
        if (is64) {
            f = (int)((const long long*)from_idx)[i];
            t = (int)((const long long*)to_idx)[i];
        } else {
            f = ((const int*)from_idx)[i];
            t = ((const int*)to_idx)[i];
        }
    }
    const bool match = (i < nnz) & (t >= t_lo) & (t < t_hi) & (f >= 0) & (f < num_from);
    unsigned mask = __ballot_sync(0xFFFFFFFFu, match);

    // Loop over matching items only; broadcast (f,t), whole warp moves the
    // 512B row. W=4 items per iteration -> MLP=4 on the gather path.
    while (mask) {
        int s[W];
#pragma unroll
        for (int k = 0; k < W; k++) {
            s[k] = mask ? (__ffs(mask) - 1) : -1;
            if (s[k] >= 0) mask &= mask - 1;
        }

        int fk[W], tk[W];
#pragma unroll
        for (int k = 0; k < W; k++) {
            int srck = s[k] < 0 ? 0 : s[k];
            fk[k] = __shfl_sync(0xFFFFFFFFu, f, srck);
            tk[k] = __shfl_sync(0xFFFFFFFFu, t, srck);
        }

        // Front-batched independent 512B gathers, evict-normal (__ldg) to
        // capture the ~1.3-1.6x per-row reuse within a pass.
        float4 v[W];
#pragma unroll
        for (int k = 0; k < W; k++) {
            if (s[k] >= 0)
                v[k] = __ldg(reinterpret_cast<const float4*>(
                                 x + (long long)fk[k] * D) + lane);
        }

        // Vector reductions (no return) with evict_last cache hint.
#pragma unroll
        for (int k = 0; k < W; k++) {
            if (s[k] >= 0) {
                float* dst = out + (long long)tk[k] * D + lane * 4;
                asm volatile("red.global.add.L2::cache_hint.v4.f32 [%0], {%1, %2, %3, %4}, %5;"
                             :: "l"(dst), "f"(v[k].x), "f"(v[k].y), "f"(v[k].z), "f"(v[k].w),
                                "l"(pol)
                             : "memory");
            }
        }
    }
}

extern "C" void kernel_launch(void* const* d_in, const int* in_sizes, int n_in,
                              void* d_out, int out_size) {
    const float* x = (const float*)d_in[0];
    const void*  from_idx = d_in[1];
    const void*  to_idx   = d_in[2];
    float* out = (float*)d_out;

    int nnz = in_sizes[1];
    int num_from = (int)((long long)in_sizes[0] / D);
    int num_to   = (int)((long long)out_size / D);

    int rows_per_pass = (num_to + NPASS - 1) / NPASS;

    int threads = 256;
    unsigned blocks = (unsigned)(((long long)nnz + threads - 1) / threads);

    for (int p = 0; p < NPASS; p++) {
        int t_lo = p * rows_per_pass;
        int t_hi = t_lo + rows_per_pass;
        if (t_hi > num_to) t_hi = num_to;
        if (t_lo >= t_hi) break;

        // Zero this partition with evict_last stores right before its pass.
        long long n4 = (long long)(t_hi - t_lo) * D / 4;
        zero_evict_last_kernel<<<2048, 256>>>(
            (float4*)(out + (long long)t_lo * D), n4);

        gather_scatter_pass_kernel<<<blocks, threads>>>(
            x, from_idx, to_idx, out, nnz, num_from, t_lo, t_hi);
    }
}

// round 17
// speedup vs baseline: 1.1344x; 1.1344x over previous
#include <cuda_runtime.h>
#include <stdint.h>

#define D 128        // feature dim: one warp = one row (32 lanes x float4)
#define NPASS 2      // output partitions (each 64 MB; stays L2-resident because
                     // the gather stream is L2-evict-first)
#define W 4          // items per warp-iteration (R9 best: 40 regs, occ ~61%)

__global__ void gather_scatter_pass_kernel(const float* __restrict__ x,
                                           const void* __restrict__ from_idx,
                                           const void* __restrict__ to_idx,
                                           float* __restrict__ out,
                                           int nnz,
                                           int num_from,
                                           int t_lo,
                                           int t_hi) {
    // Per-block index-dtype detection (int32 vs int64). Index values fit in
    // 32 bits, so for int64 data every odd 32-bit word is 0.
    __shared__ int s_is64;
    if (threadIdx.x == 0) {
        const unsigned int* w = (const unsigned int*)from_idx;
        s_is64 = (w[1] == 0u && w[3] == 0u && w[5] == 0u && w[7] == 0u) ? 1 : 0;
    }
    __syncthreads();
    const int is64 = s_is64;

    // Gather-load policy: L2 evict-first (protect the out partition, proven in
    // R9 vs R12 A/B) while L1 stays evict-normal (unlike __ldcs) to capture
    // row reuse in the 32 MB aggregate L1.
    unsigned long long pol;
    asm("createpolicy.fractional.L2::evict_first.b64 %0, 1.0;" : "=l"(pol));

    const int gtid = blockIdx.x * blockDim.x + threadIdx.x;
    const int lane = threadIdx.x & 31;
    const int i = gtid;  // each LANE owns one nonzero (coalesced index loads)

    int f = 0, t = -1;
    if (i < nnz) {
        if (is64) {
            f = (int)((const long long*)from_idx)[i];
            t = (int)((const long long*)to_idx)[i];
        } else {
            f = ((const int*)from_idx)[i];
            t = ((const int*)to_idx)[i];
        }
    }
    const bool match = (i < nnz) & (t >= t_lo) & (t < t_hi) & (f >= 0) & (f < num_from);
    unsigned mask = __ballot_sync(0xFFFFFFFFu, match);

    // Loop over matching items only; broadcast (f,t), whole warp moves the
    // 512B row. W=4 items per iteration -> MLP=4 on the gather path.
    while (mask) {
        int s[W];
#pragma unroll
        for (int k = 0; k < W; k++) {
            s[k] = mask ? (__ffs(mask) - 1) : -1;
            if (s[k] >= 0) mask &= mask - 1;
        }

        int fk[W], tk[W];
#pragma unroll
        for (int k = 0; k < W; k++) {
            int srck = s[k] < 0 ? 0 : s[k];
            fk[k] = __shfl_sync(0xFFFFFFFFu, f, srck);
            tk[k] = __shfl_sync(0xFFFFFFFFu, t, srck);
        }

        // Front-batched independent 512B gathers: L1 evict-normal,
        // L2 evict-first via cache_hint policy.
        float4 v[W];
#pragma unroll
        for (int k = 0; k < W; k++) {
            if (s[k] >= 0) {
                const float* src = x + (long long)fk[k] * D + lane * 4;
                asm volatile("ld.global.nc.L2::cache_hint.v4.f32 {%0,%1,%2,%3}, [%4], %5;"
                             : "=f"(v[k].x), "=f"(v[k].y), "=f"(v[k].z), "=f"(v[k].w)
                             : "l"(src), "l"(pol));
            }
        }

        // Vector reductions (no return), 16B per op, into L2-resident partition.
#pragma unroll
        for (int k = 0; k < W; k++) {
            if (s[k] >= 0) {
                float* dst = out + (long long)tk[k] * D + lane * 4;
                asm volatile("red.global.add.v4.f32 [%0], {%1, %2, %3, %4};"
                             :: "l"(dst), "f"(v[k].x), "f"(v[k].y), "f"(v[k].z), "f"(v[k].w)
                             : "memory");
            }
        }
    }
}

extern "C" void kernel_launch(void* const* d_in, const int* in_sizes, int n_in,
                              void* d_out, int out_size) {
    const float* x = (const float*)d_in[0];
    const void*  from_idx = d_in[1];
    const void*  to_idx   = d_in[2];
    float* out = (float*)d_out;

    int nnz = in_sizes[1];
    int num_from = (int)((long long)in_sizes[0] / D);
    int num_to   = (int)((long long)out_size / D);

    int rows_per_pass = (num_to + NPASS - 1) / NPASS;

    int threads = 256;
    unsigned blocks = (unsigned)(((long long)nnz + threads - 1) / threads);

    for (int p = 0; p < NPASS; p++) {
        int t_lo = p * rows_per_pass;
        int t_hi = t_lo + rows_per_pass;
        if (t_hi > num_to) t_hi = num_to;
        if (t_lo >= t_hi) break;

        // Zero this partition right before its pass so the zeroed lines are
        // still L2-resident when the atomics arrive.
        cudaMemsetAsync(out + (long long)t_lo * D, 0,
                        (size_t)(t_hi - t_lo) * D * sizeof(float));

        gather_scatter_pass_kernel<<<blocks, threads>>>(
            x, from_idx, to_idx, out, nnz, num_from, t_lo, t_hi);
    }
}